// round 1
// baseline (speedup 1.0000x reference)
#include <cuda_runtime.h>
#include <cuda_bf16.h>
#include <cstddef>

// Problem constants
constexpr int kNA  = 500000;
constexpr int kNB  = 500000;
constexpr int kE   = 1000000;
constexpr int kHID = 64;
constexpr int kOUT = 32;

// ---------------- static scratch (allocation-free rule) ----------------
__device__ __align__(256) float g_s_ab[kNB];          // scalar agg of x_a over ei_ab -> b nodes
__device__ __align__(256) float g_s_ba[kNA];          // scalar agg of x_b over ei_ba -> a nodes
__device__ __align__(256) float g_s_aa[kNA];          // scalar agg of x_a over ei_aa -> a nodes
__device__ __align__(256) float g_zA_aa[(size_t)kNA * kOUT]; // relu(ha) @ W_rel2[2]
__device__ __align__(256) float g_zA_ab[(size_t)kNA * kOUT]; // relu(ha) @ W_rel2[0]
__device__ __align__(256) float g_zB_ba[(size_t)kNB * kOUT]; // relu(hb) @ W_rel2[1]
__device__ int g_idx64;                               // 1 if edge indices are int64, 0 if int32

// ---------------- small PTX helpers (sm_103a packed f32 FMA) ----------------
__device__ __forceinline__ unsigned long long pack2(float a, float b) {
    unsigned long long r;
    asm("mov.b64 %0, {%1, %2};" : "=l"(r) : "f"(a), "f"(b));
    return r;
}
__device__ __forceinline__ void fma2(unsigned long long& d, unsigned long long a, unsigned long long b) {
    asm("fma.rn.f32x2 %0, %1, %2, %0;" : "+l"(d) : "l"(a), "l"(b));
}

// ---------------- index-width detection ----------------
// jnp int64 silently downcasts to int32 when jax x64 is off. Detect which
// layout the buffer actually has: for little-endian int64 values < 2^31,
// every odd 32-bit word is zero. P(false positive with int32 data) ~ (2e-6)^64.
__global__ void detect_kernel(const int* __restrict__ ei_words) {
    if (blockIdx.x == 0 && threadIdx.x == 0) {
        int nz = 0;
        for (int q = 0; q < 64; ++q) nz |= ei_words[2 * q + 1];
        g_idx64 = (nz == 0) ? 1 : 0;
    }
}

__device__ __forceinline__ void load_edge(const int* __restrict__ ei, int e, int& src, int& dst) {
    if (g_idx64) { src = ei[2 * e]; dst = ei[2 * kE + 2 * e]; }
    else         { src = ei[e];     dst = ei[kE + e]; }
}

// ---------------- phase 0: zero scalar accumulators ----------------
__global__ void zero_s_kernel() {
    int i = blockIdx.x * blockDim.x + threadIdx.x;
    if (i < kNA) { g_s_ab[i] = 0.f; g_s_ba[i] = 0.f; g_s_aa[i] = 0.f; }
}

// ---------------- phase 1: scalar edge scatter (layer 1 agg) ----------------
__global__ void scatter_scalar_kernel(const float* __restrict__ x,
                                      const int* __restrict__ ei, int which) {
    int e = blockIdx.x * blockDim.x + threadIdx.x;
    if (e >= kE) return;
    int src, dst;
    load_edge(ei, e, src, dst);
    float v = x[src];
    float* s = (which == 0) ? g_s_ab : (which == 1) ? g_s_ba : g_s_aa;
    atomicAdd(&s[dst], v);
}

// ---------------- phase 2: fused per-node kernels ----------------
// a-nodes: ha[j] = relu(s_ba*Wr1[1][j] + s_aa*Wr1[2][j] + x_a*(Wo1[1][j]+Wo1[2][j]) + b1[1][j]+b1[2][j])
// projections: cols 0-31 = W_rel2[2] (->zA_aa), 32-63 = W_rel2[0] (->zA_ab),
//              64-95 = W_root2[1]+W_root2[2] (+bias -> out rows [0,NA))
__global__ void __launch_bounds__(256) node_a_kernel(
    const float* __restrict__ x_a,
    const float* __restrict__ W_rel1, const float* __restrict__ W_root1, const float* __restrict__ b1,
    const float* __restrict__ W_rel2, const float* __restrict__ W_root2, const float* __restrict__ b2,
    float* __restrict__ out) {
    __shared__ __align__(16) float4 sL1[kHID];
    __shared__ __align__(16) float  sWc[kHID * 96];
    __shared__ float sBias[kOUT];

    int tid = threadIdx.x;
    for (int j = tid; j < kHID; j += blockDim.x) {
        sL1[j] = make_float4(W_rel1[1 * kHID + j], W_rel1[2 * kHID + j],
                             W_root1[1 * kHID + j] + W_root1[2 * kHID + j],
                             b1[kHID + j] + b1[2 * kHID + j]);
    }
    for (int idx = tid; idx < kHID * 96; idx += blockDim.x) {
        int j = idx / 96, k = idx % 96;
        float v;
        if (k < 32)      v = W_rel2[2 * 2048 + j * 32 + k];
        else if (k < 64) v = W_rel2[0 * 2048 + j * 32 + (k - 32)];
        else             v = W_root2[1 * 2048 + j * 32 + (k - 64)] +
                             W_root2[2 * 2048 + j * 32 + (k - 64)];
        sWc[idx] = v;
    }
    if (tid < kOUT) sBias[tid] = b2[kOUT + tid] + b2[2 * kOUT + tid];
    __syncthreads();

    int i = blockIdx.x * blockDim.x + tid;
    if (i >= kNA) return;
    float sba = g_s_ba[i], saa = g_s_aa[i], xa = x_a[i];

    #pragma unroll 1
    for (int pass = 0; pass < 3; ++pass) {
        unsigned long long acc[16];
        if (pass == 2) {
            #pragma unroll
            for (int m = 0; m < 16; ++m) acc[m] = pack2(sBias[2 * m], sBias[2 * m + 1]);
        } else {
            #pragma unroll
            for (int m = 0; m < 16; ++m) acc[m] = 0ULL;
        }
        const ulonglong2* Wp = reinterpret_cast<const ulonglong2*>(sWc) + pass * 8;
        #pragma unroll 8
        for (int j = 0; j < kHID; ++j) {
            float4 w = sL1[j];
            float h = fmaxf(fmaf(sba, w.x, fmaf(saa, w.y, fmaf(xa, w.z, w.w))), 0.f);
            unsigned long long hp = pack2(h, h);
            const ulonglong2* Wr = Wp + j * 24;   // row stride: 96 floats = 24 ulonglong2
            #pragma unroll
            for (int q = 0; q < 8; ++q) {
                ulonglong2 wv = Wr[q];
                fma2(acc[2 * q],     hp, wv.x);
                fma2(acc[2 * q + 1], hp, wv.y);
            }
        }
        float* dstf = (pass == 0) ? (g_zA_aa + (size_t)i * kOUT)
                    : (pass == 1) ? (g_zA_ab + (size_t)i * kOUT)
                                  : (out + (size_t)i * kOUT);
        ulonglong2* dst = reinterpret_cast<ulonglong2*>(dstf);
        #pragma unroll
        for (int q = 0; q < 8; ++q) dst[q] = make_ulonglong2(acc[2 * q], acc[2 * q + 1]);
    }
}

// b-nodes: hb[j] = relu(s_ab*Wr1[0][j] + x_b*Wo1[0][j] + b1[0][j])
// projections: cols 0-31 = W_rel2[1] (->zB_ba), 32-63 = W_root2[0] (+b2[0] -> out rows [NA, NA+NB))
__global__ void __launch_bounds__(256) node_b_kernel(
    const float* __restrict__ x_b,
    const float* __restrict__ W_rel1, const float* __restrict__ W_root1, const float* __restrict__ b1,
    const float* __restrict__ W_rel2, const float* __restrict__ W_root2, const float* __restrict__ b2,
    float* __restrict__ out) {
    __shared__ __align__(16) float4 sL1[kHID];
    __shared__ __align__(16) float  sWc[kHID * 64];
    __shared__ float sBias[kOUT];

    int tid = threadIdx.x;
    for (int j = tid; j < kHID; j += blockDim.x) {
        sL1[j] = make_float4(W_rel1[j], W_root1[j], b1[j], 0.f);
    }
    for (int idx = tid; idx < kHID * 64; idx += blockDim.x) {
        int j = idx / 64, k = idx % 64;
        float v;
        if (k < 32) v = W_rel2[1 * 2048 + j * 32 + k];
        else        v = W_root2[0 * 2048 + j * 32 + (k - 32)];
        sWc[idx] = v;
    }
    if (tid < kOUT) sBias[tid] = b2[tid];
    __syncthreads();

    int i = blockIdx.x * blockDim.x + tid;
    if (i >= kNB) return;
    float sab = g_s_ab[i], xb = x_b[i];

    #pragma unroll 1
    for (int pass = 0; pass < 2; ++pass) {
        unsigned long long acc[16];
        if (pass == 1) {
            #pragma unroll
            for (int m = 0; m < 16; ++m) acc[m] = pack2(sBias[2 * m], sBias[2 * m + 1]);
        } else {
            #pragma unroll
            for (int m = 0; m < 16; ++m) acc[m] = 0ULL;
        }
        const ulonglong2* Wp = reinterpret_cast<const ulonglong2*>(sWc) + pass * 8;
        #pragma unroll 8
        for (int j = 0; j < kHID; ++j) {
            float4 w = sL1[j];
            float h = fmaxf(fmaf(sab, w.x, fmaf(xb, w.y, w.z)), 0.f);
            unsigned long long hp = pack2(h, h);
            const ulonglong2* Wr = Wp + j * 16;   // row stride: 64 floats = 16 ulonglong2
            #pragma unroll
            for (int q = 0; q < 8; ++q) {
                ulonglong2 wv = Wr[q];
                fma2(acc[2 * q],     hp, wv.x);
                fma2(acc[2 * q + 1], hp, wv.y);
            }
        }
        float* dstf = (pass == 0) ? (g_zB_ba + (size_t)i * kOUT)
                                  : (out + ((size_t)kNA + i) * kOUT);
        ulonglong2* dst = reinterpret_cast<ulonglong2*>(dstf);
        #pragma unroll
        for (int q = 0; q < 8; ++q) dst[q] = make_ulonglong2(acc[2 * q], acc[2 * q + 1]);
    }
}

// ---------------- phase 3: 32-wide edge scatter (layer 2 agg) ----------------
// 8 lanes per edge, each moving one float4 via vector reduction (red.global.add.v4.f32).
__global__ void scatter_vec_kernel(const int* __restrict__ ei, int which,
                                   float* __restrict__ out) {
    int t = blockIdx.x * blockDim.x + threadIdx.x;
    int e = t >> 3;
    if (e >= kE) return;
    int c = t & 7;
    int src, dst;
    load_edge(ei, e, src, dst);
    const float* z = (which == 0) ? g_zA_ab : (which == 1) ? g_zB_ba : g_zA_aa;
    float* ob = (which == 0) ? (out + (size_t)kNA * kOUT) : out;
    float4 v = reinterpret_cast<const float4*>(z + (size_t)src * kOUT)[c];
    float* addr = ob + (size_t)dst * kOUT + c * 4;
    asm volatile("red.global.add.v4.f32 [%0], {%1, %2, %3, %4};"
                 :: "l"(addr), "f"(v.x), "f"(v.y), "f"(v.z), "f"(v.w) : "memory");
}

// ---------------- launch ----------------
extern "C" void kernel_launch(void* const* d_in, const int* in_sizes, int n_in,
                              void* d_out, int out_size) {
    const float* x_a     = (const float*)d_in[0];
    const float* x_b     = (const float*)d_in[1];
    const int*   ei_ab   = (const int*)d_in[2];   // width handled at runtime
    const int*   ei_ba   = (const int*)d_in[3];
    const int*   ei_aa   = (const int*)d_in[4];
    const float* W_rel1  = (const float*)d_in[5];
    const float* W_root1 = (const float*)d_in[6];
    const float* b1      = (const float*)d_in[7];
    const float* W_rel2  = (const float*)d_in[8];
    const float* W_root2 = (const float*)d_in[9];
    const float* b2      = (const float*)d_in[10];
    float* out = (float*)d_out;

    const int nodeBlocks = (kNA + 255) / 256;   // 1954
    const int edgeBlocks = (kE + 255) / 256;    // 3907
    const int vecBlocks  = (kE * 8) / 256;      // 31250

    detect_kernel<<<1, 32>>>(ei_ab);
    zero_s_kernel<<<nodeBlocks, 256>>>();
    scatter_scalar_kernel<<<edgeBlocks, 256>>>(x_a, ei_ab, 0);
    scatter_scalar_kernel<<<edgeBlocks, 256>>>(x_b, ei_ba, 1);
    scatter_scalar_kernel<<<edgeBlocks, 256>>>(x_a, ei_aa, 2);
    node_a_kernel<<<nodeBlocks, 256>>>(x_a, W_rel1, W_root1, b1, W_rel2, W_root2, b2, out);
    node_b_kernel<<<nodeBlocks, 256>>>(x_b, W_rel1, W_root1, b1, W_rel2, W_root2, b2, out);
    scatter_vec_kernel<<<vecBlocks, 256>>>(ei_ab, 0, out);
    scatter_vec_kernel<<<vecBlocks, 256>>>(ei_ba, 1, out);
    scatter_vec_kernel<<<vecBlocks, 256>>>(ei_aa, 2, out);
}